// round 8
// baseline (speedup 1.0000x reference)
#include <cuda_runtime.h>
#include <cstdint>

#define THREADS 128
#define ROWS 128

typedef unsigned long long ull;

// ---- packed f32x2 helpers (Blackwell dual-fp32 pipe) ----
__device__ __forceinline__ ull f2x2_fma(ull a, ull b, ull c) {
    ull d; asm("fma.rn.f32x2 %0, %1, %2, %3;" : "=l"(d) : "l"(a), "l"(b), "l"(c)); return d;
}
__device__ __forceinline__ ull f2x2_add(ull a, ull b) {
    ull d; asm("add.rn.f32x2 %0, %1, %2;" : "=l"(d) : "l"(a), "l"(b)); return d;
}
__device__ __forceinline__ ull f2x2_pack(float lo, float hi) {
    ull d; asm("mov.b64 %0, {%1, %2};" : "=l"(d) : "f"(lo), "f"(hi)); return d;
}
__device__ __forceinline__ void f2x2_unpack(ull v, float& lo, float& hi) {
    asm("mov.b64 {%0, %1}, %2;" : "=f"(lo), "=f"(hi) : "l"(v));
}

// ---- shared memory layout (float offsets) ----
// Small always-live tables first, then the overlay region:
//   phase A (until xp-pack):  xs = x transposed [64][129]  (8256 floats)
//   phase B (MLP):            w1t [128][68] (8704 floats)   <- staged at boundary
// w2 [128][32] (4096 floats) sits PAST xs's end, so it is staged up front.
#define OB1    0       // [128]
#define OB2    128     // [32]
#define OMEAN  160     // [64]
#define OSCL   224     // [64]
#define OENCW  288     // [8][8][4]
#define OENCB  544     // [8][4]
#define OSRCW  576     // [4][16]
#define OSRCB  640     // [16]
#define ODSTW  656     // [4][16]
#define ODSTB  720     // [16]
#define ODECW  736     // [96][2]
#define ODECB  928     // [2]
#define OATTA  930     // A[2][4][4] pre-scaled by 1/sqrt(8)
#define OATTV  962     // V[2][4]
#define OMLP2  976     // mlp decoder partials [128][2]
#define OVL    1232    // overlay base (16B aligned)
#define OW1T   OVL                 // phase B: w1t [128][68]
#define OXS    OVL                 // phase A: xs [64][129]  (8256 <= 8704, fits in w1t's span)
#define OW2    (OVL + 8704)        // w2 [128][32], disjoint from xs
#define SMEM_FLOATS (OVL + 8704 + 4096)   // 14032 floats
#define SMEM_BYTES  (SMEM_FLOATS * 4)     // 56128 B -> 4 CTAs/SM

__global__ void __launch_bounds__(THREADS, 4)
ggan_kernel(const float* __restrict__ gx,
            const float* __restrict__ g_mean, const float* __restrict__ g_std,
            const float* __restrict__ g_w1,   const float* __restrict__ g_b1,
            const float* __restrict__ g_w2,   const float* __restrict__ g_b2,
            const float* __restrict__ g_encw, const float* __restrict__ g_encb,
            const float* __restrict__ g_srcw, const float* __restrict__ g_srcb,
            const float* __restrict__ g_dstw, const float* __restrict__ g_dstb,
            const float* __restrict__ g_decw, const float* __restrict__ g_decb,
            float2* __restrict__ gout)
{
    extern __shared__ float sm[];
    float* b1s  = sm + OB1;
    float* b2s  = sm + OB2;
    float* mnv  = sm + OMEAN;
    float* sclv = sm + OSCL;
    float* encw = sm + OENCW;
    float* encb = sm + OENCB;
    float* srcw = sm + OSRCW;
    float* srcb = sm + OSRCB;
    float* dstw = sm + ODSTW;
    float* dstb = sm + ODSTB;
    float* decw = sm + ODECW;
    float* decb = sm + ODECB;
    float* attA = sm + OATTA;
    float* attV = sm + OATTV;
    float* mlp2 = sm + OMLP2;
    float* w1t  = sm + OW1T;
    float* xs   = sm + OXS;
    float* w2s  = sm + OW2;

    const int tid = threadIdx.x;
    const float inv_sqrt8 = 0.35355339059327373f;

    // ================= stage small tables + w2 + x tile =================
    b1s[tid] = g_b1[tid];
    for (int i = tid; i < 256; i += THREADS) encw[i] = g_encw[i];
    for (int i = tid; i < 192; i += THREADS) decw[i] = g_decw[i];
    if (tid < 64) {
        mnv[tid]  = g_mean[tid];
        sclv[tid] = 1.0f / (g_std[tid] + 1e-8f);
        srcw[tid] = g_srcw[tid];
        dstw[tid] = g_dstw[tid];
    }
    if (tid < 32) { b2s[tid] = g_b2[tid]; encb[tid] = g_encb[tid]; }
    if (tid < 16) { srcb[tid] = g_srcb[tid]; dstb[tid] = g_dstb[tid]; }
    if (tid < 2)  decb[tid] = g_decb[tid];

    {   // w2 (region disjoint from xs) staged up front
        const float4* w2g = (const float4*)g_w2;
        float4* w2sh = (float4*)w2s;
        for (int i = tid; i < 1024; i += THREADS) w2sh[i] = w2g[i];
    }

    const size_t rowBase = (size_t)blockIdx.x * ROWS;
    const float4* xg = (const float4*)(gx + rowBase * 64);
    for (int i = tid; i < ROWS * 16; i += THREADS) {
        float4 v = xg[i];
        int r0 = i >> 4, c = (i & 15) * 4;
        xs[(c + 0) * 129 + r0] = v.x;
        xs[(c + 1) * 129 + r0] = v.y;
        xs[(c + 2) * 129 + r0] = v.z;
        xs[(c + 3) * 129 + r0] = v.w;
    }
    __syncthreads();

    // ================= precompute attention tables =================
    // score'_gk = h_g^T A h_k + v . h_k   (k-independent terms cancel in softmax)
    if (tid < 32) {
        int h = tid >> 4, e = (tid >> 2) & 3, e2 = tid & 3;
        float s = 0.0f;
        #pragma unroll
        for (int a = 0; a < 8; a++)
            s += srcw[e * 16 + h * 8 + a] * dstw[e2 * 16 + h * 8 + a];
        attA[tid] = s * inv_sqrt8;
    } else if (tid < 40) {
        int h = (tid - 32) >> 2, e2 = (tid - 32) & 3;
        float s = 0.0f;
        #pragma unroll
        for (int a = 0; a < 8; a++)
            s += srcb[h * 8 + a] * dstw[e2 * 16 + h * 8 + a];
        attV[tid - 32] = s * inv_sqrt8;
    }

    const int r = tid;

    // ================= per-group encoders =================
    float hv[32];
    #pragma unroll
    for (int g = 0; g < 8; g++) {
        float xn[8];
        #pragma unroll
        for (int f = 0; f < 8; f++) {
            int d = g * 8 + f;
            xn[f] = (xs[d * 129 + r] - mnv[d]) * sclv[d];
        }
        #pragma unroll
        for (int e = 0; e < 4; e++) {
            float s = encb[g * 4 + e];
            #pragma unroll
            for (int f = 0; f < 8; f++)
                s += xn[f] * encw[g * 32 + f * 4 + e];
            hv[g * 4 + e] = fmaxf(s, 0.0f);
        }
    }

    // decoder accumulators; fold h contribution now
    float o0 = decb[0], o1 = decb[1];
    #pragma unroll
    for (int i = 0; i < 32; i++) {
        o0 += hv[i] * decw[(32 + i) * 2 + 0];
        o1 += hv[i] * decw[(32 + i) * 2 + 1];
    }

    __syncthreads();   // attA/attV visible

    // ================= GAT attention (factored form, scalar accum) =================
    float attf[32];
    #pragma unroll
    for (int i = 0; i < 32; i++) attf[i] = 0.0f;

    #pragma unroll
    for (int hd = 0; hd < 2; hd++) {
        const float* Ah = attA + hd * 16;
        const float* Vh = attV + hd * 4;
        float t[32], q[8];
        #pragma unroll
        for (int k = 0; k < 8; k++) {
            float s = 0.0f;
            #pragma unroll
            for (int e = 0; e < 4; e++) s += Vh[e] * hv[k * 4 + e];
            q[k] = s;
            #pragma unroll
            for (int e = 0; e < 4; e++) {
                float u = 0.0f;
                #pragma unroll
                for (int e2 = 0; e2 < 4; e2++)
                    u += Ah[e * 4 + e2] * hv[k * 4 + e2];
                t[k * 4 + e] = u;
            }
        }
        #pragma unroll
        for (int g = 0; g < 8; g++) {
            float sc[8], mx = -1e30f;
            #pragma unroll
            for (int k = 0; k < 8; k++) {
                float s = q[k];
                #pragma unroll
                for (int e = 0; e < 4; e++)
                    s += hv[g * 4 + e] * t[k * 4 + e];
                sc[k] = s;
                mx = fmaxf(mx, s);
            }
            float ssum = 0.0f;
            #pragma unroll
            for (int k = 0; k < 8; k++) { sc[k] = __expf(sc[k] - mx); ssum += sc[k]; }
            float inv = 1.0f / ssum;
            #pragma unroll
            for (int k = 0; k < 8; k++) {
                float w = sc[k] * inv;
                #pragma unroll
                for (int e = 0; e < 4; e++)
                    attf[g * 4 + e] += w * hv[k * 4 + e];
            }
        }
    }

    // fold att_out contribution
    #pragma unroll
    for (int i = 0; i < 32; i++) {
        o0 += attf[i] * decw[(64 + i) * 2 + 0];
        o1 += attf[i] * decw[(64 + i) * 2 + 1];
    }

    // ================= cooperative-pair MLP setup =================
    // Lane pair p = lane>>1, half h = lane&1. Pair handles rows R0 = warp*32+p
    // and R1 = warp*32+16+p; each lane owns K-half h*32..+31 and output half
    // h*16..+15. h=1 reads weight blocks rotated by 4 (bank-disjoint vs h=0);
    // x registers are packed in the SAME rotated order (compile-time indices).
    const int lane = tid & 31, warp = tid >> 5;
    const int p = lane >> 1, h = lane & 1;
    const int R0 = warp * 32 + p, R1 = warp * 32 + 16 + p;
    const int rot = h * 4;

    ull xpa[16], xpb[16];
    #pragma unroll
    for (int i = 0; i < 8; i++) {
        int d = h * 32 + (((i + rot) & 7) << 2);
        xpa[2 * i]     = f2x2_pack(xs[(d + 0) * 129 + R0], xs[(d + 1) * 129 + R0]);
        xpa[2 * i + 1] = f2x2_pack(xs[(d + 2) * 129 + R0], xs[(d + 3) * 129 + R0]);
        xpb[2 * i]     = f2x2_pack(xs[(d + 0) * 129 + R1], xs[(d + 1) * 129 + R1]);
        xpb[2 * i + 1] = f2x2_pack(xs[(d + 2) * 129 + R1], xs[(d + 3) * 129 + R1]);
    }

    __syncthreads();   // xs fully consumed
    // stage w1t into the overlay region (transposed; coalesced global reads)
    for (int i = tid; i < 64 * 128; i += THREADS) {
        int d = i >> 7, hh = i & 127;
        w1t[hh * 68 + d] = g_w1[i];
    }
    __syncthreads();   // w1t staged

    // ================= cooperative MLP (64->128 relu ->32) =================
    ull acc0[8], acc1[8];
    {
        const ull* b2p = (const ull*)(b2s + h * 16);
        #pragma unroll
        for (int k = 0; k < 8; k++) { acc0[k] = b2p[k]; acc1[k] = b2p[k]; }
    }

    #pragma unroll 2
    for (int hid = 0; hid < 128; hid++) {
        const ulonglong2* wrow = (const ulonglong2*)(w1t + hid * 68 + h * 32);
        ull a0 = 0ull, a1 = 0ull, a2 = 0ull, a3 = 0ull;
        #pragma unroll
        for (int i = 0; i < 8; i++) {
            ulonglong2 W = wrow[(i + rot) & 7];
            a0 = f2x2_fma(xpa[2 * i],     W.x, a0);
            a1 = f2x2_fma(xpa[2 * i + 1], W.y, a1);
            a2 = f2x2_fma(xpb[2 * i],     W.x, a2);
            a3 = f2x2_fma(xpb[2 * i + 1], W.y, a3);
        }
        float l0, h0f, l1, h1f;
        f2x2_unpack(f2x2_add(a0, a1), l0, h0f);
        f2x2_unpack(f2x2_add(a2, a3), l1, h1f);
        float s0 = l0 + h0f, s1 = l1 + h1f;
        s0 += __shfl_xor_sync(0xffffffffu, s0, 1);
        s1 += __shfl_xor_sync(0xffffffffu, s1, 1);
        float bb = b1s[hid];
        float act0 = fmaxf(s0 + bb, 0.0f);
        float act1 = fmaxf(s1 + bb, 0.0f);
        ull ap0 = f2x2_pack(act0, act0);
        ull ap1 = f2x2_pack(act1, act1);
        const ulonglong2* w2row = (const ulonglong2*)(w2s + hid * 32 + h * 16);
        #pragma unroll
        for (int k = 0; k < 4; k++) {
            ulonglong2 W = w2row[k];
            acc0[2 * k]     = f2x2_fma(ap0, W.x, acc0[2 * k]);
            acc0[2 * k + 1] = f2x2_fma(ap0, W.y, acc0[2 * k + 1]);
            acc1[2 * k]     = f2x2_fma(ap1, W.x, acc1[2 * k]);
            acc1[2 * k + 1] = f2x2_fma(ap1, W.y, acc1[2 * k + 1]);
        }
    }

    // ---- fold x_hat contribution to decoder (per-lane partial, pair-reduced) ----
    float p00 = 0.0f, p10 = 0.0f, p01 = 0.0f, p11 = 0.0f;
    #pragma unroll
    for (int j = 0; j < 8; j++) {
        int o = h * 16 + 2 * j;
        float a, b;
        f2x2_unpack(acc0[j], a, b);
        a = fmaxf(a, 0.0f); b = fmaxf(b, 0.0f);
        p00 += a * decw[o * 2 + 0] + b * decw[(o + 1) * 2 + 0];
        p10 += a * decw[o * 2 + 1] + b * decw[(o + 1) * 2 + 1];
        f2x2_unpack(acc1[j], a, b);
        a = fmaxf(a, 0.0f); b = fmaxf(b, 0.0f);
        p01 += a * decw[o * 2 + 0] + b * decw[(o + 1) * 2 + 0];
        p11 += a * decw[o * 2 + 1] + b * decw[(o + 1) * 2 + 1];
    }
    p00 += __shfl_xor_sync(0xffffffffu, p00, 1);
    p10 += __shfl_xor_sync(0xffffffffu, p10, 1);
    p01 += __shfl_xor_sync(0xffffffffu, p01, 1);
    p11 += __shfl_xor_sync(0xffffffffu, p11, 1);
    if (h == 0) {
        mlp2[R0 * 2 + 0] = p00;
        mlp2[R0 * 2 + 1] = p10;
    } else {
        mlp2[R1 * 2 + 0] = p01;
        mlp2[R1 * 2 + 1] = p11;
    }
    __syncthreads();

    o0 += mlp2[tid * 2 + 0];
    o1 += mlp2[tid * 2 + 1];
    gout[rowBase + tid] = make_float2(o0, o1);
}

extern "C" void kernel_launch(void* const* d_in, const int* in_sizes, int n_in,
                              void* d_out, int out_size)
{
    const float* x      = (const float*)d_in[0];
    const float* nmean  = (const float*)d_in[1];
    const float* nstd   = (const float*)d_in[2];
    const float* w1     = (const float*)d_in[3];
    const float* b1     = (const float*)d_in[4];
    const float* w2     = (const float*)d_in[5];
    const float* b2     = (const float*)d_in[6];
    const float* encwp  = (const float*)d_in[7];
    const float* encbp  = (const float*)d_in[8];
    const float* srcwp  = (const float*)d_in[9];
    const float* srcbp  = (const float*)d_in[10];
    const float* dstwp  = (const float*)d_in[11];
    const float* dstbp  = (const float*)d_in[12];
    const float* decwp  = (const float*)d_in[13];
    const float* decbp  = (const float*)d_in[14];
    float2* out = (float2*)d_out;

    int B = in_sizes[0] / 64;
    int grid = B / ROWS;

    cudaFuncSetAttribute(ggan_kernel, cudaFuncAttributeMaxDynamicSharedMemorySize, SMEM_BYTES);

    ggan_kernel<<<grid, THREADS, SMEM_BYTES>>>(
        x, nmean, nstd, w1, b1, w2, b2,
        encwp, encbp, srcwp, srcbp, dstwp, dstbp, decwp, decbp, out);
}

// round 9
// speedup vs baseline: 1.0046x; 1.0046x over previous
#include <cuda_runtime.h>
#include <cstdint>

#define THREADS 128
#define ROWS 128

typedef unsigned long long ull;

// ---- packed f32x2 helpers (Blackwell dual-fp32 pipe) ----
__device__ __forceinline__ ull f2x2_fma(ull a, ull b, ull c) {
    ull d; asm("fma.rn.f32x2 %0, %1, %2, %3;" : "=l"(d) : "l"(a), "l"(b), "l"(c)); return d;
}
__device__ __forceinline__ ull f2x2_add(ull a, ull b) {
    ull d; asm("add.rn.f32x2 %0, %1, %2;" : "=l"(d) : "l"(a), "l"(b)); return d;
}
__device__ __forceinline__ ull f2x2_pack(float lo, float hi) {
    ull d; asm("mov.b64 %0, {%1, %2};" : "=l"(d) : "f"(lo), "f"(hi)); return d;
}
__device__ __forceinline__ void f2x2_unpack(ull v, float& lo, float& hi) {
    asm("mov.b64 {%0, %1}, %2;" : "=f"(lo), "=f"(hi) : "l"(v));
}

// ---- shared memory layout (float offsets) ----
// Small always-live tables first, then the overlay region:
//   phase A (until xp-pack):  xs = x transposed [64][129]  (8256 floats)
//   phase B (MLP):            w1t [128][68] (8704 floats)   <- staged at boundary
// w2 [128][32] (4096 floats) sits PAST xs's end, so it is staged up front.
#define OB1    0       // [128]
#define OB2    128     // [32]
#define OMEAN  160     // [64]
#define OSCL   224     // [64]
#define OENCW  288     // [8][8][4]
#define OENCB  544     // [8][4]
#define OSRCW  576     // [4][16]
#define OSRCB  640     // [16]
#define ODSTW  656     // [4][16]
#define ODSTB  720     // [16]
#define ODECW  736     // [96][2]
#define ODECB  928     // [2]
#define OATTA  930     // A[2][4][4] pre-scaled by 1/sqrt(8)
#define OATTV  962     // V[2][4]
#define OMLP2  976     // mlp decoder partials [128][2]
#define OVL    1232    // overlay base (16B aligned)
#define OW1T   OVL                 // phase B: w1t [128][68]
#define OXS    OVL                 // phase A: xs [64][129]  (8256 <= 8704, fits in w1t's span)
#define OW2    (OVL + 8704)        // w2 [128][32], disjoint from xs
#define SMEM_FLOATS (OVL + 8704 + 4096)   // 14032 floats
#define SMEM_BYTES  (SMEM_FLOATS * 4)     // 56128 B -> 4 CTAs/SM

__global__ void __launch_bounds__(THREADS, 4)
ggan_kernel(const float* __restrict__ gx,
            const float* __restrict__ g_mean, const float* __restrict__ g_std,
            const float* __restrict__ g_w1,   const float* __restrict__ g_b1,
            const float* __restrict__ g_w2,   const float* __restrict__ g_b2,
            const float* __restrict__ g_encw, const float* __restrict__ g_encb,
            const float* __restrict__ g_srcw, const float* __restrict__ g_srcb,
            const float* __restrict__ g_dstw, const float* __restrict__ g_dstb,
            const float* __restrict__ g_decw, const float* __restrict__ g_decb,
            float2* __restrict__ gout)
{
    extern __shared__ float sm[];
    float* b1s  = sm + OB1;
    float* b2s  = sm + OB2;
    float* mnv  = sm + OMEAN;
    float* sclv = sm + OSCL;
    float* encw = sm + OENCW;
    float* encb = sm + OENCB;
    float* srcw = sm + OSRCW;
    float* srcb = sm + OSRCB;
    float* dstw = sm + ODSTW;
    float* dstb = sm + ODSTB;
    float* decw = sm + ODECW;
    float* decb = sm + ODECB;
    float* attA = sm + OATTA;
    float* attV = sm + OATTV;
    float* mlp2 = sm + OMLP2;
    float* w1t  = sm + OW1T;
    float* xs   = sm + OXS;
    float* w2s  = sm + OW2;

    const int tid = threadIdx.x;
    const float inv_sqrt8 = 0.35355339059327373f;

    // ================= stage small tables + w2 + x tile =================
    b1s[tid] = g_b1[tid];
    for (int i = tid; i < 256; i += THREADS) encw[i] = g_encw[i];
    for (int i = tid; i < 192; i += THREADS) decw[i] = g_decw[i];
    if (tid < 64) {
        mnv[tid]  = g_mean[tid];
        sclv[tid] = 1.0f / (g_std[tid] + 1e-8f);
        srcw[tid] = g_srcw[tid];
        dstw[tid] = g_dstw[tid];
    }
    if (tid < 32) { b2s[tid] = g_b2[tid]; encb[tid] = g_encb[tid]; }
    if (tid < 16) { srcb[tid] = g_srcb[tid]; dstb[tid] = g_dstb[tid]; }
    if (tid < 2)  decb[tid] = g_decb[tid];

    {   // w2 (region disjoint from xs) staged up front
        const float4* w2g = (const float4*)g_w2;
        float4* w2sh = (float4*)w2s;
        for (int i = tid; i < 1024; i += THREADS) w2sh[i] = w2g[i];
    }

    const size_t rowBase = (size_t)blockIdx.x * ROWS;
    const float4* xg = (const float4*)(gx + rowBase * 64);
    for (int i = tid; i < ROWS * 16; i += THREADS) {
        float4 v = xg[i];
        int r0 = i >> 4, c = (i & 15) * 4;
        xs[(c + 0) * 129 + r0] = v.x;
        xs[(c + 1) * 129 + r0] = v.y;
        xs[(c + 2) * 129 + r0] = v.z;
        xs[(c + 3) * 129 + r0] = v.w;
    }
    __syncthreads();

    // ================= precompute attention tables =================
    // score'_gk = h_g^T A h_k + v . h_k   (k-independent terms cancel in softmax)
    if (tid < 32) {
        int h = tid >> 4, e = (tid >> 2) & 3, e2 = tid & 3;
        float s = 0.0f;
        #pragma unroll
        for (int a = 0; a < 8; a++)
            s += srcw[e * 16 + h * 8 + a] * dstw[e2 * 16 + h * 8 + a];
        attA[tid] = s * inv_sqrt8;
    } else if (tid < 40) {
        int h = (tid - 32) >> 2, e2 = (tid - 32) & 3;
        float s = 0.0f;
        #pragma unroll
        for (int a = 0; a < 8; a++)
            s += srcb[h * 8 + a] * dstw[e2 * 16 + h * 8 + a];
        attV[tid - 32] = s * inv_sqrt8;
    }

    const int r = tid;

    // ================= per-group encoders =================
    float hv[32];
    #pragma unroll
    for (int g = 0; g < 8; g++) {
        float xn[8];
        #pragma unroll
        for (int f = 0; f < 8; f++) {
            int d = g * 8 + f;
            xn[f] = (xs[d * 129 + r] - mnv[d]) * sclv[d];
        }
        #pragma unroll
        for (int e = 0; e < 4; e++) {
            float s = encb[g * 4 + e];
            #pragma unroll
            for (int f = 0; f < 8; f++)
                s += xn[f] * encw[g * 32 + f * 4 + e];
            hv[g * 4 + e] = fmaxf(s, 0.0f);
        }
    }

    // decoder accumulators; fold h contribution now
    float o0 = decb[0], o1 = decb[1];
    #pragma unroll
    for (int i = 0; i < 32; i++) {
        o0 += hv[i] * decw[(32 + i) * 2 + 0];
        o1 += hv[i] * decw[(32 + i) * 2 + 1];
    }

    __syncthreads();   // attA/attV visible

    // ================= GAT attention (factored form, scalar accum) =================
    float attf[32];
    #pragma unroll
    for (int i = 0; i < 32; i++) attf[i] = 0.0f;

    #pragma unroll
    for (int hd = 0; hd < 2; hd++) {
        const float* Ah = attA + hd * 16;
        const float* Vh = attV + hd * 4;
        float t[32], q[8];
        #pragma unroll
        for (int k = 0; k < 8; k++) {
            float s = 0.0f;
            #pragma unroll
            for (int e = 0; e < 4; e++) s += Vh[e] * hv[k * 4 + e];
            q[k] = s;
            #pragma unroll
            for (int e = 0; e < 4; e++) {
                float u = 0.0f;
                #pragma unroll
                for (int e2 = 0; e2 < 4; e2++)
                    u += Ah[e * 4 + e2] * hv[k * 4 + e2];
                t[k * 4 + e] = u;
            }
        }
        #pragma unroll
        for (int g = 0; g < 8; g++) {
            float sc[8], mx = -1e30f;
            #pragma unroll
            for (int k = 0; k < 8; k++) {
                float s = q[k];
                #pragma unroll
                for (int e = 0; e < 4; e++)
                    s += hv[g * 4 + e] * t[k * 4 + e];
                sc[k] = s;
                mx = fmaxf(mx, s);
            }
            float ssum = 0.0f;
            #pragma unroll
            for (int k = 0; k < 8; k++) { sc[k] = __expf(sc[k] - mx); ssum += sc[k]; }
            float inv = 1.0f / ssum;
            #pragma unroll
            for (int k = 0; k < 8; k++) {
                float w = sc[k] * inv;
                #pragma unroll
                for (int e = 0; e < 4; e++)
                    attf[g * 4 + e] += w * hv[k * 4 + e];
            }
        }
    }

    // fold att_out contribution
    #pragma unroll
    for (int i = 0; i < 32; i++) {
        o0 += attf[i] * decw[(64 + i) * 2 + 0];
        o1 += attf[i] * decw[(64 + i) * 2 + 1];
    }

    // ================= cooperative-pair MLP setup =================
    // Lane pair p = lane>>1, half h = lane&1. Pair handles rows R0 = warp*32+p
    // and R1 = warp*32+16+p; each lane owns K-half h*32..+31 and output half
    // h*16..+15. h=1 reads weight blocks rotated by 4 (bank-disjoint vs h=0);
    // x registers are packed in the SAME rotated order (compile-time indices).
    const int lane = tid & 31, warp = tid >> 5;
    const int p = lane >> 1, h = lane & 1;
    const int R0 = warp * 32 + p, R1 = warp * 32 + 16 + p;
    const int rot = h * 4;

    ull xpa[16], xpb[16];
    #pragma unroll
    for (int i = 0; i < 8; i++) {
        int d = h * 32 + (((i + rot) & 7) << 2);
        xpa[2 * i]     = f2x2_pack(xs[(d + 0) * 129 + R0], xs[(d + 1) * 129 + R0]);
        xpa[2 * i + 1] = f2x2_pack(xs[(d + 2) * 129 + R0], xs[(d + 3) * 129 + R0]);
        xpb[2 * i]     = f2x2_pack(xs[(d + 0) * 129 + R1], xs[(d + 1) * 129 + R1]);
        xpb[2 * i + 1] = f2x2_pack(xs[(d + 2) * 129 + R1], xs[(d + 3) * 129 + R1]);
    }

    __syncthreads();   // xs fully consumed
    // stage w1t into the overlay region (transposed; coalesced global reads)
    for (int i = tid; i < 64 * 128; i += THREADS) {
        int d = i >> 7, hh = i & 127;
        w1t[hh * 68 + d] = g_w1[i];
    }
    __syncthreads();   // w1t staged

    // ================= cooperative MLP (64->128 relu ->32) =================
    ull acc0[8], acc1[8];
    {
        const ull* b2p = (const ull*)(b2s + h * 16);
        #pragma unroll
        for (int k = 0; k < 8; k++) { acc0[k] = b2p[k]; acc1[k] = b2p[k]; }
    }

    #pragma unroll 2
    for (int hid = 0; hid < 128; hid++) {
        const ulonglong2* wrow = (const ulonglong2*)(w1t + hid * 68 + h * 32);
        ull a0 = 0ull, a1 = 0ull, a2 = 0ull, a3 = 0ull;
        #pragma unroll
        for (int i = 0; i < 8; i++) {
            ulonglong2 W = wrow[(i + rot) & 7];
            a0 = f2x2_fma(xpa[2 * i],     W.x, a0);
            a1 = f2x2_fma(xpa[2 * i + 1], W.y, a1);
            a2 = f2x2_fma(xpb[2 * i],     W.x, a2);
            a3 = f2x2_fma(xpb[2 * i + 1], W.y, a3);
        }
        float l0, h0f, l1, h1f;
        f2x2_unpack(f2x2_add(a0, a1), l0, h0f);
        f2x2_unpack(f2x2_add(a2, a3), l1, h1f);
        float s0 = l0 + h0f, s1 = l1 + h1f;
        s0 += __shfl_xor_sync(0xffffffffu, s0, 1);
        s1 += __shfl_xor_sync(0xffffffffu, s1, 1);
        float bb = b1s[hid];
        float act0 = fmaxf(s0 + bb, 0.0f);
        float act1 = fmaxf(s1 + bb, 0.0f);
        ull ap0 = f2x2_pack(act0, act0);
        ull ap1 = f2x2_pack(act1, act1);
        const ulonglong2* w2row = (const ulonglong2*)(w2s + hid * 32 + h * 16);
        #pragma unroll
        for (int k = 0; k < 4; k++) {
            ulonglong2 W = w2row[k];
            acc0[2 * k]     = f2x2_fma(ap0, W.x, acc0[2 * k]);
            acc0[2 * k + 1] = f2x2_fma(ap0, W.y, acc0[2 * k + 1]);
            acc1[2 * k]     = f2x2_fma(ap1, W.x, acc1[2 * k]);
            acc1[2 * k + 1] = f2x2_fma(ap1, W.y, acc1[2 * k + 1]);
        }
    }

    // ---- fold x_hat contribution to decoder (per-lane partial, pair-reduced) ----
    float p00 = 0.0f, p10 = 0.0f, p01 = 0.0f, p11 = 0.0f;
    #pragma unroll
    for (int j = 0; j < 8; j++) {
        int o = h * 16 + 2 * j;
        float a, b;
        f2x2_unpack(acc0[j], a, b);
        a = fmaxf(a, 0.0f); b = fmaxf(b, 0.0f);
        p00 += a * decw[o * 2 + 0] + b * decw[(o + 1) * 2 + 0];
        p10 += a * decw[o * 2 + 1] + b * decw[(o + 1) * 2 + 1];
        f2x2_unpack(acc1[j], a, b);
        a = fmaxf(a, 0.0f); b = fmaxf(b, 0.0f);
        p01 += a * decw[o * 2 + 0] + b * decw[(o + 1) * 2 + 0];
        p11 += a * decw[o * 2 + 1] + b * decw[(o + 1) * 2 + 1];
    }
    p00 += __shfl_xor_sync(0xffffffffu, p00, 1);
    p10 += __shfl_xor_sync(0xffffffffu, p10, 1);
    p01 += __shfl_xor_sync(0xffffffffu, p01, 1);
    p11 += __shfl_xor_sync(0xffffffffu, p11, 1);
    if (h == 0) {
        mlp2[R0 * 2 + 0] = p00;
        mlp2[R0 * 2 + 1] = p10;
    } else {
        mlp2[R1 * 2 + 0] = p01;
        mlp2[R1 * 2 + 1] = p11;
    }
    __syncthreads();

    o0 += mlp2[tid * 2 + 0];
    o1 += mlp2[tid * 2 + 1];
    gout[rowBase + tid] = make_float2(o0, o1);
}

extern "C" void kernel_launch(void* const* d_in, const int* in_sizes, int n_in,
                              void* d_out, int out_size)
{
    const float* x      = (const float*)d_in[0];
    const float* nmean  = (const float*)d_in[1];
    const float* nstd   = (const float*)d_in[2];
    const float* w1     = (const float*)d_in[3];
    const float* b1     = (const float*)d_in[4];
    const float* w2     = (const float*)d_in[5];
    const float* b2     = (const float*)d_in[6];
    const float* encwp  = (const float*)d_in[7];
    const float* encbp  = (const float*)d_in[8];
    const float* srcwp  = (const float*)d_in[9];
    const float* srcbp  = (const float*)d_in[10];
    const float* dstwp  = (const float*)d_in[11];
    const float* dstbp  = (const float*)d_in[12];
    const float* decwp  = (const float*)d_in[13];
    const float* decbp  = (const float*)d_in[14];
    float2* out = (float2*)d_out;

    int B = in_sizes[0] / 64;
    int grid = B / ROWS;

    cudaFuncSetAttribute(ggan_kernel, cudaFuncAttributeMaxDynamicSharedMemorySize, SMEM_BYTES);

    ggan_kernel<<<grid, THREADS, SMEM_BYTES>>>(
        x, nmean, nstd, w1, b1, w2, b2,
        encwp, encbp, srcwp, srcbp, dstwp, dstbp, decwp, decbp, out);
}